// round 6
// baseline (speedup 1.0000x reference)
#include <cuda_runtime.h>
#include <cuda_bf16.h>
#include <cuda_fp16.h>
#include <cstdint>

#define NNODES 100000
#define EDGES_MAX 1600000
#define DIM 128
#define SCAN_BLK 4096
#define NB_SCAN ((NNODES + SCAN_BLK - 1) / SCAN_BLK)

// ---------------------------------------------------------------------------
// Device-global scratch (no allocations allowed anywhere)
// ---------------------------------------------------------------------------
__device__ float g_agg[NNODES * DIM];
__device__ float g_h1[NNODES * DIM];
__device__ __half g_xh[NNODES * DIM];   // fp16 copy of x for gathers
__device__ int   g_is64;
__device__ __nv_bfloat16 g_wt1_hi[DIM * DIM];
__device__ __nv_bfloat16 g_wt1_lo[DIM * DIM];
__device__ __nv_bfloat16 g_wt2_hi[DIM * DIM];
__device__ __nv_bfloat16 g_wt2_lo[DIM * DIM];
// CSR build
__device__ int g_cnt[NNODES];
__device__ int g_rowptr[NNODES + 1];
__device__ int g_cur[NNODES];
__device__ int g_blksum[NB_SCAN + 1];
__device__ int g_esrc[EDGES_MAX];

// ---------------------------------------------------------------------------
// helpers
// ---------------------------------------------------------------------------
__device__ __forceinline__ uint32_t smem_u32(const void* p) {
    uint32_t a;
    asm("{ .reg .u64 t; cvta.to.shared.u64 t, %1; cvt.u32.u64 %0, t; }"
        : "=r"(a) : "l"(p));
    return a;
}
__device__ __forceinline__ void ldsm4(uint32_t* r, uint32_t addr) {
    asm volatile("ldmatrix.sync.aligned.m8n8.x4.shared.b16 {%0,%1,%2,%3}, [%4];"
                 : "=r"(r[0]), "=r"(r[1]), "=r"(r[2]), "=r"(r[3]) : "r"(addr));
}
__device__ __forceinline__ void mma_bf16(float* d, const uint32_t* a,
                                         uint32_t b0, uint32_t b1) {
    asm volatile(
        "mma.sync.aligned.m16n8k16.row.col.f32.bf16.bf16.f32 "
        "{%0,%1,%2,%3}, {%4,%5,%6,%7}, {%8,%9}, {%0,%1,%2,%3};"
        : "+f"(d[0]), "+f"(d[1]), "+f"(d[2]), "+f"(d[3])
        : "r"(a[0]), "r"(a[1]), "r"(a[2]), "r"(a[3]), "r"(b0), "r"(b1));
}
__device__ __forceinline__ int load_idx(const void* ei, long long pos) {
    return g_is64 ? (int)((const long long*)ei)[pos] : ((const int*)ei)[pos];
}

// ---------------------------------------------------------------------------
// edge_index dtype detection (int64 ids < 2^31 -> odd words all zero)
// ---------------------------------------------------------------------------
__global__ void detect_kernel(const unsigned int* __restrict__ w) {
    if (threadIdx.x == 0 && blockIdx.x == 0) {
        int allzero = 1;
        for (int i = 1; i < 256; i += 2)
            if (w[i] != 0u) { allzero = 0; break; }
        g_is64 = allzero;
    }
}

// ---------------------------------------------------------------------------
// x -> fp16 copy (for halved gather traffic)
// ---------------------------------------------------------------------------
__global__ void xh_kernel(const float4* __restrict__ x, int n4) {
    int i = blockIdx.x * blockDim.x + threadIdx.x;
    if (i >= n4) return;
    float4 v = x[i];
    __half2* o = (__half2*)g_xh;
    o[2 * i]     = __floats2half2_rn(v.x, v.y);
    o[2 * i + 1] = __floats2half2_rn(v.z, v.w);
}

// ---------------------------------------------------------------------------
// CSR build: zero -> histogram -> 3-phase exclusive scan -> reorder
// ---------------------------------------------------------------------------
__global__ void zero_cnt_kernel(int N) {
    int i = blockIdx.x * blockDim.x + threadIdx.x;
    if (i < N) g_cnt[i] = 0;
}

__global__ void hist_kernel(const void* __restrict__ ei, int E) {
    int i0 = (blockIdx.x * blockDim.x + threadIdx.x) * 4;
    if (i0 + 4 <= E) {
        int d0 = load_idx(ei, (long long)E + i0);
        int d1 = load_idx(ei, (long long)E + i0 + 1);
        int d2 = load_idx(ei, (long long)E + i0 + 2);
        int d3 = load_idx(ei, (long long)E + i0 + 3);
        atomicAdd(&g_cnt[d0], 1);
        atomicAdd(&g_cnt[d1], 1);
        atomicAdd(&g_cnt[d2], 1);
        atomicAdd(&g_cnt[d3], 1);
    } else {
        for (int i = i0; i < E; i++)
            atomicAdd(&g_cnt[load_idx(ei, (long long)E + i)], 1);
    }
}

__global__ void scan1_kernel(int N) {  // 512 threads; 4096 elems/block
    __shared__ int sh[512];
    int t = threadIdx.x, b = blockIdx.x;
    int base = b * SCAN_BLK + t * 8;
    int v[8], s = 0;
#pragma unroll
    for (int j = 0; j < 8; j++) {
        int idx = base + j;
        v[j] = (idx < N) ? g_cnt[idx] : 0;
        s += v[j];
    }
    sh[t] = s;
    __syncthreads();
    for (int off = 1; off < 512; off <<= 1) {
        int y = (t >= off) ? sh[t - off] : 0;
        __syncthreads();
        sh[t] += y;
        __syncthreads();
    }
    int run = sh[t] - s;
#pragma unroll
    for (int j = 0; j < 8; j++) {
        int idx = base + j;
        if (idx < N) g_rowptr[idx] = run;
        run += v[j];
    }
    if (t == 511) g_blksum[b] = sh[511];
}

__global__ void scan2_kernel(int nb) {
    if (threadIdx.x == 0 && blockIdx.x == 0) {
        int acc = 0;
        for (int i = 0; i < nb; i++) {
            int v = g_blksum[i];
            g_blksum[i] = acc;
            acc += v;
        }
    }
}

__global__ void scan3_kernel(int N, int E) {
    int i = blockIdx.x * blockDim.x + threadIdx.x;
    if (i < N) {
        int v = g_rowptr[i] + g_blksum[i / SCAN_BLK];
        g_rowptr[i] = v;
        g_cur[i] = v;
    }
    if (i == 0) g_rowptr[N] = E;
}

__global__ void reorder_kernel(const void* __restrict__ ei, int E) {
    int i0 = (blockIdx.x * blockDim.x + threadIdx.x) * 4;
    if (i0 + 4 <= E) {
        int s0 = load_idx(ei, i0),     s1 = load_idx(ei, i0 + 1);
        int s2 = load_idx(ei, i0 + 2), s3 = load_idx(ei, i0 + 3);
        int d0 = load_idx(ei, (long long)E + i0);
        int d1 = load_idx(ei, (long long)E + i0 + 1);
        int d2 = load_idx(ei, (long long)E + i0 + 2);
        int d3 = load_idx(ei, (long long)E + i0 + 3);
        g_esrc[atomicAdd(&g_cur[d0], 1)] = s0;
        g_esrc[atomicAdd(&g_cur[d1], 1)] = s1;
        g_esrc[atomicAdd(&g_cur[d2], 1)] = s2;
        g_esrc[atomicAdd(&g_cur[d3], 1)] = s3;
    } else {
        for (int i = i0; i < E; i++) {
            int src = load_idx(ei, i);
            int dst = load_idx(ei, (long long)E + i);
            g_esrc[atomicAdd(&g_cur[dst], 1)] = src;
        }
    }
}

// ---------------------------------------------------------------------------
// Aggregation: one warp per node.
// agg[i] = (1+eps)*x[i] (fp32) + sum_j xh[esrc[j]] (fp16 gather, fp32 acc).
// Lane covers cols [lane*4, lane*4+4): uint2 = 4 halfs per gather.
// ---------------------------------------------------------------------------
__global__ void agg_kernel(const float4* __restrict__ x,
                           const float* __restrict__ eps, int N) {
    int w = (blockIdx.x * blockDim.x + threadIdx.x) >> 5;
    if (w >= N) return;
    int lane = threadIdx.x & 31;
    float s = 1.0f + eps[0];

    float4 a = x[(size_t)w * 32 + lane];
    float4 acc = make_float4(a.x * s, a.y * s, a.z * s, a.w * s);

    const uint2* xh2 = (const uint2*)g_xh;  // 4 halfs per uint2, 32 per row
    int j  = g_rowptr[w];
    int r1 = g_rowptr[w + 1];

#pragma unroll 1
    for (; j + 4 <= r1; j += 4) {
        int s0 = g_esrc[j],     s1 = g_esrc[j + 1];
        int s2 = g_esrc[j + 2], s3 = g_esrc[j + 3];
        uint2 v0 = xh2[(size_t)s0 * 32 + lane];
        uint2 v1 = xh2[(size_t)s1 * 32 + lane];
        uint2 v2 = xh2[(size_t)s2 * 32 + lane];
        uint2 v3 = xh2[(size_t)s3 * 32 + lane];
#pragma unroll
        for (int q = 0; q < 4; q++) {
            uint2 v = (q == 0) ? v0 : (q == 1) ? v1 : (q == 2) ? v2 : v3;
            float2 f0 = __half22float2(*reinterpret_cast<__half2*>(&v.x));
            float2 f1 = __half22float2(*reinterpret_cast<__half2*>(&v.y));
            acc.x += f0.x; acc.y += f0.y; acc.z += f1.x; acc.w += f1.y;
        }
    }
    for (; j < r1; j++) {
        uint2 v = xh2[(size_t)g_esrc[j] * 32 + lane];
        float2 f0 = __half22float2(*reinterpret_cast<__half2*>(&v.x));
        float2 f1 = __half22float2(*reinterpret_cast<__half2*>(&v.y));
        acc.x += f0.x; acc.y += f0.y; acc.z += f1.x; acc.w += f1.y;
    }
    ((float4*)g_agg)[(size_t)w * 32 + lane] = acc;
}

// ---------------------------------------------------------------------------
// Legacy fallback path (if E > EDGES_MAX): init + atomic scatter (fp32)
// ---------------------------------------------------------------------------
__global__ void init_kernel(const float4* __restrict__ x,
                            const float* __restrict__ eps, int n4) {
    float s = 1.0f + eps[0];
    float4* agg = (float4*)g_agg;
    int i = blockIdx.x * blockDim.x + threadIdx.x;
    int stride = gridDim.x * blockDim.x;
    for (; i < n4; i += stride) {
        float4 v = x[i];
        v.x *= s; v.y *= s; v.z *= s; v.w *= s;
        agg[i] = v;
    }
}

__global__ void scatter_kernel(const float4* __restrict__ x,
                               const void* __restrict__ ei, int E) {
    int t = blockIdx.x * blockDim.x + threadIdx.x;
    int e = t >> 5;
    if (e >= E) return;
    int lane = t & 31;
    int src = load_idx(ei, e);
    int dst = load_idx(ei, (long long)E + e);
    float4 v = x[(size_t)src * 32 + lane];
    float* q = g_agg + (size_t)dst * 128 + lane * 4;
    asm volatile("red.global.add.v4.f32 [%0], {%1,%2,%3,%4};"
                 :: "l"(q), "f"(v.x), "f"(v.y), "f"(v.z), "f"(v.w)
                 : "memory");
}

// ---------------------------------------------------------------------------
// Weight prep: Wt[n][k] = W[k][n], split fp32 -> bf16 hi + lo.
// ---------------------------------------------------------------------------
__global__ void prep_w_kernel(const float* __restrict__ W1,
                              const float* __restrict__ W2) {
    int i = blockIdx.x * blockDim.x + threadIdx.x;
    if (i >= 2 * DIM * DIM) return;
    const float* W = (i < DIM * DIM) ? W1 : W2;
    __nv_bfloat16* H = (i < DIM * DIM) ? g_wt1_hi : g_wt2_hi;
    __nv_bfloat16* L = (i < DIM * DIM) ? g_wt1_lo : g_wt2_lo;
    int j = i & (DIM * DIM - 1);
    int nIdx = j >> 7;
    int k = j & 127;
    float w = W[k * DIM + nIdx];
    __nv_bfloat16 h = __float2bfloat16(w);
    H[j] = h;
    L[j] = __float2bfloat16(w - __bfloat162float(h));
}

// ---------------------------------------------------------------------------
// Tensor-core GEMM via mma.sync (family-level PTX). bf16 hi/lo 3-pass.
// CTA: 256 rows x 128 cols; 8 warps x 32 rows.
// ---------------------------------------------------------------------------
#define PADB 272
#define SM_AH 0
#define SM_AL 69632
#define SM_BH 139264
#define SM_BL 174080
#define SMEM_GEMM_BYTES 208896

__global__ void __launch_bounds__(256, 1)
gemm_mma_kernel(const float* __restrict__ A,
                const __nv_bfloat16* __restrict__ Bh,
                const __nv_bfloat16* __restrict__ Bl,
                const float* __restrict__ bias,
                float* __restrict__ C, int n, int relu) {
    extern __shared__ char smem[];
    uint32_t sb = smem_u32(smem);
    int tid = threadIdx.x, wid = tid >> 5, lane = tid & 31;
    int row0 = blockIdx.x * 256;

    const float4* A4 = (const float4*)A;
#pragma unroll
    for (int i = 0; i < 32; i++) {
        int idx = tid + 256 * i;
        int r = idx >> 5, c4 = idx & 31;
        int gr = row0 + r;
        float4 v = (gr < n) ? A4[(size_t)gr * 32 + c4]
                            : make_float4(0.f, 0.f, 0.f, 0.f);
        __nv_bfloat16 h0 = __float2bfloat16(v.x);
        __nv_bfloat16 h1 = __float2bfloat16(v.y);
        __nv_bfloat16 h2 = __float2bfloat16(v.z);
        __nv_bfloat16 h3 = __float2bfloat16(v.w);
        __nv_bfloat162 ph0 = __halves2bfloat162(h0, h1);
        __nv_bfloat162 ph1 = __halves2bfloat162(h2, h3);
        __nv_bfloat162 pl0 = __halves2bfloat162(
            __float2bfloat16(v.x - __bfloat162float(h0)),
            __float2bfloat16(v.y - __bfloat162float(h1)));
        __nv_bfloat162 pl1 = __halves2bfloat162(
            __float2bfloat16(v.z - __bfloat162float(h2)),
            __float2bfloat16(v.w - __bfloat162float(h3)));
        char* ph = smem + SM_AH + r * PADB + c4 * 8;
        char* pl = smem + SM_AL + r * PADB + c4 * 8;
        *(uint2*)ph = make_uint2(*reinterpret_cast<uint32_t*>(&ph0),
                                 *reinterpret_cast<uint32_t*>(&ph1));
        *(uint2*)pl = make_uint2(*reinterpret_cast<uint32_t*>(&pl0),
                                 *reinterpret_cast<uint32_t*>(&pl1));
    }

    const uint2* bh2 = (const uint2*)Bh;
    const uint2* bl2 = (const uint2*)Bl;
#pragma unroll
    for (int i = 0; i < 16; i++) {
        int idx = tid + 256 * i;
        int r = idx >> 5, c4 = idx & 31;
        *(uint2*)(smem + SM_BH + r * PADB + c4 * 8) = bh2[idx];
        *(uint2*)(smem + SM_BL + r * PADB + c4 * 8) = bl2[idx];
    }
    __syncthreads();

    int lr = lane & 7;
    int li = lane >> 3;
    uint32_t aoff = (uint32_t)((wid * 32 + lr + (li & 1) * 8) * PADB +
                               ((li >> 1) * 8) * 2);
    uint32_t boff = (uint32_t)((lr + (li >> 1) * 8) * PADB + ((li & 1) * 8) * 2);

    float acc[2][16][4];
#pragma unroll
    for (int mt = 0; mt < 2; mt++)
#pragma unroll
        for (int nt = 0; nt < 16; nt++)
#pragma unroll
            for (int q = 0; q < 4; q++) acc[mt][nt][q] = 0.0f;

    for (int ks = 0; ks < 8; ks++) {
        uint32_t kadd = ks * 32;
        uint32_t ah[2][4], al[2][4];
        ldsm4(ah[0], sb + SM_AH + aoff + kadd);
        ldsm4(ah[1], sb + SM_AH + aoff + 16 * PADB + kadd);
        ldsm4(al[0], sb + SM_AL + aoff + kadd);
        ldsm4(al[1], sb + SM_AL + aoff + 16 * PADB + kadd);
#pragma unroll
        for (int ng = 0; ng < 8; ng++) {
            uint32_t nadd = ng * 16 * PADB;
            uint32_t bh[4], bl[4];
            ldsm4(bh, sb + SM_BH + boff + nadd + kadd);
            ldsm4(bl, sb + SM_BL + boff + nadd + kadd);
#pragma unroll
            for (int mt = 0; mt < 2; mt++) {
                mma_bf16(acc[mt][2 * ng],     ah[mt], bh[0], bh[1]);
                mma_bf16(acc[mt][2 * ng],     ah[mt], bl[0], bl[1]);
                mma_bf16(acc[mt][2 * ng],     al[mt], bh[0], bh[1]);
                mma_bf16(acc[mt][2 * ng + 1], ah[mt], bh[2], bh[3]);
                mma_bf16(acc[mt][2 * ng + 1], ah[mt], bl[2], bl[3]);
                mma_bf16(acc[mt][2 * ng + 1], al[mt], bh[2], bh[3]);
            }
        }
    }

#pragma unroll
    for (int nt = 0; nt < 16; nt++) {
        int col = nt * 8 + (lane & 3) * 2;
        float2 bv = *(const float2*)(bias + col);
#pragma unroll
        for (int mt = 0; mt < 2; mt++) {
            int r0 = row0 + wid * 32 + mt * 16 + (lane >> 2);
            float* a = acc[mt][nt];
            float v0 = a[0] + bv.x, v1 = a[1] + bv.y;
            float v2 = a[2] + bv.x, v3 = a[3] + bv.y;
            if (relu) {
                v0 = fmaxf(v0, 0.f); v1 = fmaxf(v1, 0.f);
                v2 = fmaxf(v2, 0.f); v3 = fmaxf(v3, 0.f);
            }
            if (r0 < n)     *(float2*)(C + (size_t)r0 * 128 + col) = make_float2(v0, v1);
            if (r0 + 8 < n) *(float2*)(C + (size_t)(r0 + 8) * 128 + col) = make_float2(v2, v3);
        }
    }
}

// ---------------------------------------------------------------------------
extern "C" void kernel_launch(void* const* d_in, const int* in_sizes, int n_in,
                              void* d_out, int out_size) {
    const float* x   = (const float*)d_in[0];
    const void*  ei  = d_in[1];
    const float* W1  = (const float*)d_in[2];
    const float* b1  = (const float*)d_in[3];
    const float* W2  = (const float*)d_in[4];
    const float* b2  = (const float*)d_in[5];
    const float* eps = (const float*)d_in[6];

    int N = in_sizes[0] / DIM;
    int E = in_sizes[1] / 2;

    float* agg_ptr = nullptr;
    float* h1_ptr  = nullptr;
    __nv_bfloat16 *wt1h, *wt1l, *wt2h, *wt2l;
    cudaGetSymbolAddress((void**)&agg_ptr, g_agg);
    cudaGetSymbolAddress((void**)&h1_ptr,  g_h1);
    cudaGetSymbolAddress((void**)&wt1h, g_wt1_hi);
    cudaGetSymbolAddress((void**)&wt1l, g_wt1_lo);
    cudaGetSymbolAddress((void**)&wt2h, g_wt2_hi);
    cudaGetSymbolAddress((void**)&wt2l, g_wt2_lo);

    detect_kernel<<<1, 32>>>((const unsigned int*)ei);
    prep_w_kernel<<<(2 * DIM * DIM + 255) / 256, 256>>>(W1, W2);

    if (E <= EDGES_MAX && N <= NNODES) {
        int n4 = N * (DIM / 4);
        xh_kernel<<<(n4 + 255) / 256, 256>>>((const float4*)x, n4);
        zero_cnt_kernel<<<(N + 255) / 256, 256>>>(N);
        int nthr4 = (E + 3) / 4;
        hist_kernel<<<(nthr4 + 255) / 256, 256>>>(ei, E);
        int nb_scan = (N + SCAN_BLK - 1) / SCAN_BLK;
        scan1_kernel<<<nb_scan, 512>>>(N);
        scan2_kernel<<<1, 32>>>(nb_scan);
        scan3_kernel<<<(N + 255) / 256, 256>>>(N, E);
        reorder_kernel<<<(nthr4 + 255) / 256, 256>>>(ei, E);
        agg_kernel<<<(N * 32 + 255) / 256, 256>>>((const float4*)x, eps, N);
    } else {
        int n4 = N * (DIM / 4);
        init_kernel<<<(n4 + 255) / 256, 256>>>((const float4*)x, eps, n4);
        long long tot = (long long)E * 32;
        scatter_kernel<<<(int)((tot + 255) / 256), 256>>>((const float4*)x, ei, E);
    }

    cudaFuncSetAttribute(gemm_mma_kernel,
                         cudaFuncAttributeMaxDynamicSharedMemorySize,
                         SMEM_GEMM_BYTES);
    int nb = (N + 255) / 256;
    gemm_mma_kernel<<<nb, 256, SMEM_GEMM_BYTES>>>(agg_ptr, wt1h, wt1l, b1,
                                                  h1_ptr, N, 1);
    gemm_mma_kernel<<<nb, 256, SMEM_GEMM_BYTES>>>(h1_ptr, wt2h, wt2l, b2,
                                                  (float*)d_out, N, 0);
}

// round 7
// speedup vs baseline: 1.0816x; 1.0816x over previous
#include <cuda_runtime.h>
#include <cuda_bf16.h>
#include <cstdint>

#define NNODES 100000
#define EDGES_MAX 1600000
#define DIM 128
#define SCAN_BLK 4096
#define NB_SCAN ((NNODES + SCAN_BLK - 1) / SCAN_BLK)

// ---------------------------------------------------------------------------
// Device-global scratch (no allocations allowed anywhere)
// ---------------------------------------------------------------------------
__device__ float g_agg[NNODES * DIM];
__device__ float g_h1[NNODES * DIM];
__device__ int   g_is64;
__device__ float g_wt1[DIM * DIM];   // W1^T, tf32-rounded fp32, [n][k]
__device__ float g_wt2[DIM * DIM];   // W2^T, tf32-rounded fp32, [n][k]
// CSR build
__device__ int g_cnt[NNODES];
__device__ int g_rowptr[NNODES + 1];
__device__ int g_cur[NNODES];
__device__ int g_blksum[NB_SCAN + 1];
__device__ int g_esrc[EDGES_MAX];

// ---------------------------------------------------------------------------
// helpers
// ---------------------------------------------------------------------------
__device__ __forceinline__ uint32_t smem_u32(const void* p) {
    uint32_t a;
    asm("{ .reg .u64 t; cvta.to.shared.u64 t, %1; cvt.u32.u64 %0, t; }"
        : "=r"(a) : "l"(p));
    return a;
}
__device__ __forceinline__ void ldsm4(uint32_t* r, uint32_t addr) {
    asm volatile("ldmatrix.sync.aligned.m8n8.x4.shared.b16 {%0,%1,%2,%3}, [%4];"
                 : "=r"(r[0]), "=r"(r[1]), "=r"(r[2]), "=r"(r[3]) : "r"(addr));
}
__device__ __forceinline__ void mma_tf32(float* d, const uint32_t* a,
                                         uint32_t b0, uint32_t b1) {
    asm volatile(
        "mma.sync.aligned.m16n8k8.row.col.f32.tf32.tf32.f32 "
        "{%0,%1,%2,%3}, {%4,%5,%6,%7}, {%8,%9}, {%0,%1,%2,%3};"
        : "+f"(d[0]), "+f"(d[1]), "+f"(d[2]), "+f"(d[3])
        : "r"(a[0]), "r"(a[1]), "r"(a[2]), "r"(a[3]), "r"(b0), "r"(b1));
}
__device__ __forceinline__ uint32_t f2tf32(float f) {
    uint32_t r;
    asm("cvt.rna.tf32.f32 %0, %1;" : "=r"(r) : "f"(f));
    return r;
}
__device__ __forceinline__ int load_idx(const void* ei, long long pos) {
    return g_is64 ? (int)((const long long*)ei)[pos] : ((const int*)ei)[pos];
}

// ---------------------------------------------------------------------------
// edge_index dtype detection (int64 ids < 2^31 -> odd words all zero)
// ---------------------------------------------------------------------------
__global__ void detect_kernel(const unsigned int* __restrict__ w) {
    if (threadIdx.x == 0 && blockIdx.x == 0) {
        int allzero = 1;
        for (int i = 1; i < 256; i += 2)
            if (w[i] != 0u) { allzero = 0; break; }
        g_is64 = allzero;
    }
}

// ---------------------------------------------------------------------------
// CSR build: histogram -> 3-phase exclusive scan -> reorder
// (g_cnt is zeroed by cudaMemsetAsync in kernel_launch)
// ---------------------------------------------------------------------------
__global__ void hist_kernel(const void* __restrict__ ei, int E) {
    int i0 = (blockIdx.x * blockDim.x + threadIdx.x) * 4;
    if (i0 + 4 <= E) {
        int d0 = load_idx(ei, (long long)E + i0);
        int d1 = load_idx(ei, (long long)E + i0 + 1);
        int d2 = load_idx(ei, (long long)E + i0 + 2);
        int d3 = load_idx(ei, (long long)E + i0 + 3);
        atomicAdd(&g_cnt[d0], 1);
        atomicAdd(&g_cnt[d1], 1);
        atomicAdd(&g_cnt[d2], 1);
        atomicAdd(&g_cnt[d3], 1);
    } else {
        for (int i = i0; i < E; i++)
            atomicAdd(&g_cnt[load_idx(ei, (long long)E + i)], 1);
    }
}

__global__ void scan1_kernel(int N) {  // 512 threads; 4096 elems/block
    __shared__ int sh[512];
    int t = threadIdx.x, b = blockIdx.x;
    int base = b * SCAN_BLK + t * 8;
    int v[8], s = 0;
#pragma unroll
    for (int j = 0; j < 8; j++) {
        int idx = base + j;
        v[j] = (idx < N) ? g_cnt[idx] : 0;
        s += v[j];
    }
    sh[t] = s;
    __syncthreads();
    for (int off = 1; off < 512; off <<= 1) {
        int y = (t >= off) ? sh[t - off] : 0;
        __syncthreads();
        sh[t] += y;
        __syncthreads();
    }
    int run = sh[t] - s;
#pragma unroll
    for (int j = 0; j < 8; j++) {
        int idx = base + j;
        if (idx < N) g_rowptr[idx] = run;
        run += v[j];
    }
    if (t == 511) g_blksum[b] = sh[511];
}

__global__ void scan2_kernel(int nb) {
    if (threadIdx.x == 0 && blockIdx.x == 0) {
        int acc = 0;
        for (int i = 0; i < nb; i++) {
            int v = g_blksum[i];
            g_blksum[i] = acc;
            acc += v;
        }
    }
}

__global__ void scan3_kernel(int N, int E) {
    int i = blockIdx.x * blockDim.x + threadIdx.x;
    if (i < N) {
        int v = g_rowptr[i] + g_blksum[i / SCAN_BLK];
        g_rowptr[i] = v;
        g_cur[i] = v;
    }
    if (i == 0) g_rowptr[N] = E;
}

__global__ void reorder_kernel(const void* __restrict__ ei, int E) {
    int i0 = (blockIdx.x * blockDim.x + threadIdx.x) * 4;
    if (i0 + 4 <= E) {
        int s0 = load_idx(ei, i0),     s1 = load_idx(ei, i0 + 1);
        int s2 = load_idx(ei, i0 + 2), s3 = load_idx(ei, i0 + 3);
        int d0 = load_idx(ei, (long long)E + i0);
        int d1 = load_idx(ei, (long long)E + i0 + 1);
        int d2 = load_idx(ei, (long long)E + i0 + 2);
        int d3 = load_idx(ei, (long long)E + i0 + 3);
        g_esrc[atomicAdd(&g_cur[d0], 1)] = s0;
        g_esrc[atomicAdd(&g_cur[d1], 1)] = s1;
        g_esrc[atomicAdd(&g_cur[d2], 1)] = s2;
        g_esrc[atomicAdd(&g_cur[d3], 1)] = s3;
    } else {
        for (int i = i0; i < E; i++) {
            int src = load_idx(ei, i);
            int dst = load_idx(ei, (long long)E + i);
            g_esrc[atomicAdd(&g_cur[dst], 1)] = src;
        }
    }
}

// ---------------------------------------------------------------------------
// Aggregation: one warp per node. agg[i] = (1+eps)*x[i] + sum_j x[esrc[j]].
// fp32 float4 gathers (proven fastest variant).
// ---------------------------------------------------------------------------
__global__ void agg_kernel(const float4* __restrict__ x,
                           const float* __restrict__ eps, int N) {
    int w = (blockIdx.x * blockDim.x + threadIdx.x) >> 5;
    if (w >= N) return;
    int lane = threadIdx.x & 31;
    float s = 1.0f + eps[0];

    float4 a = x[(size_t)w * 32 + lane];
    float4 acc = make_float4(a.x * s, a.y * s, a.z * s, a.w * s);

    int j  = g_rowptr[w];
    int r1 = g_rowptr[w + 1];
    for (; j + 4 <= r1; j += 4) {
        int s0 = g_esrc[j],     s1 = g_esrc[j + 1];
        int s2 = g_esrc[j + 2], s3 = g_esrc[j + 3];
        float4 v0 = x[(size_t)s0 * 32 + lane];
        float4 v1 = x[(size_t)s1 * 32 + lane];
        float4 v2 = x[(size_t)s2 * 32 + lane];
        float4 v3 = x[(size_t)s3 * 32 + lane];
        acc.x += v0.x + v1.x + v2.x + v3.x;
        acc.y += v0.y + v1.y + v2.y + v3.y;
        acc.z += v0.z + v1.z + v2.z + v3.z;
        acc.w += v0.w + v1.w + v2.w + v3.w;
    }
    for (; j < r1; j++) {
        float4 v = x[(size_t)g_esrc[j] * 32 + lane];
        acc.x += v.x; acc.y += v.y; acc.z += v.z; acc.w += v.w;
    }
    ((float4*)g_agg)[(size_t)w * 32 + lane] = acc;
}

// ---------------------------------------------------------------------------
// Legacy fallback path (if E > EDGES_MAX): init + atomic scatter
// ---------------------------------------------------------------------------
__global__ void init_kernel(const float4* __restrict__ x,
                            const float* __restrict__ eps, int n4) {
    float s = 1.0f + eps[0];
    float4* agg = (float4*)g_agg;
    int i = blockIdx.x * blockDim.x + threadIdx.x;
    int stride = gridDim.x * blockDim.x;
    for (; i < n4; i += stride) {
        float4 v = x[i];
        v.x *= s; v.y *= s; v.z *= s; v.w *= s;
        agg[i] = v;
    }
}

__global__ void scatter_kernel(const float4* __restrict__ x,
                               const void* __restrict__ ei, int E) {
    int t = blockIdx.x * blockDim.x + threadIdx.x;
    int e = t >> 5;
    if (e >= E) return;
    int lane = t & 31;
    int src = load_idx(ei, e);
    int dst = load_idx(ei, (long long)E + e);
    float4 v = x[(size_t)src * 32 + lane];
    float* q = g_agg + (size_t)dst * 128 + lane * 4;
    asm volatile("red.global.add.v4.f32 [%0], {%1,%2,%3,%4};"
                 :: "l"(q), "f"(v.x), "f"(v.y), "f"(v.z), "f"(v.w)
                 : "memory");
}

// ---------------------------------------------------------------------------
// Weight prep: Wt[n][k] = tf32_round(W[k][n])  (fp32 bit pattern)
// ---------------------------------------------------------------------------
__global__ void prep_w_kernel(const float* __restrict__ W1,
                              const float* __restrict__ W2) {
    int i = blockIdx.x * blockDim.x + threadIdx.x;
    if (i >= 2 * DIM * DIM) return;
    const float* W = (i < DIM * DIM) ? W1 : W2;
    float* T = (i < DIM * DIM) ? g_wt1 : g_wt2;
    int j = i & (DIM * DIM - 1);
    int nIdx = j >> 7;
    int k = j & 127;
    uint32_t t = f2tf32(W[k * DIM + nIdx]);
    T[j] = __uint_as_float(t);
}

// ---------------------------------------------------------------------------
// TF32 tensor-core GEMM (single pass). C[n,128] = A[n,128] @ W + bias.
// CTA: 256 rows x 128 cols, 8 warps x 32 rows (2 m-tiles of 16 per warp).
// A staged fp32->tf32-rounded in smem [row][k], stride 132 floats (528B).
// B = Wt[n][k] (tf32-rounded at prep), stride 132 floats.
// Fragments loaded via ldmatrix reinterpreted as 8x4 b32 blocks.
// ---------------------------------------------------------------------------
#define PADW 132                       // floats per padded row
#define PADBY 528                      // bytes per padded row
#define SM_B_OFF 135168                // 256*528
#define SMEM_GEMM_BYTES 202752         // 256*528 + 128*528

__global__ void __launch_bounds__(256, 1)
gemm_tf32_kernel(const float* __restrict__ A,
                 const float* __restrict__ Bt,
                 const float* __restrict__ bias,
                 float* __restrict__ C, int n, int relu) {
    extern __shared__ char smem[];
    uint32_t sb = smem_u32(smem);
    int tid = threadIdx.x, wid = tid >> 5, lane = tid & 31;
    int row0 = blockIdx.x * 256;

    // ---- Stage A: tf32-round into padded smem ----
    const float4* A4 = (const float4*)A;
#pragma unroll
    for (int i = 0; i < 32; i++) {
        int idx = tid + 256 * i;          // float4 index in 256x32 grid
        int r = idx >> 5, c4 = idx & 31;
        int gr = row0 + r;
        float4 v = (gr < n) ? A4[(size_t)gr * 32 + c4]
                            : make_float4(0.f, 0.f, 0.f, 0.f);
        uint4 o;
        o.x = f2tf32(v.x); o.y = f2tf32(v.y);
        o.z = f2tf32(v.z); o.w = f2tf32(v.w);
        *(uint4*)(smem + r * PADBY + c4 * 16) = o;
    }

    // ---- Stage B (already tf32-rounded) into padded smem ----
    const float4* B4 = (const float4*)Bt;
#pragma unroll
    for (int i = 0; i < 16; i++) {
        int idx = tid + 256 * i;          // float4 index in 128x32 grid
        int r = idx >> 5, c4 = idx & 31;
        *(float4*)(smem + SM_B_OFF + r * PADBY + c4 * 16) = B4[idx];
    }
    __syncthreads();

    // ---- Per-lane ldmatrix addresses ----
    // A x4 (one kstep, one mtile): matrices (r0:8,k0:4)(r8:16,k0:4)(r0:8,k4:8)(r8:16,k4:8)
    int mi = lane >> 3;                   // matrix index 0..3
    int arow_base = wid * 32 + (mi & 1) * 8 + (lane & 7);
    uint32_t aaddr0 = sb + arow_base * PADBY + (mi >> 1) * 16;           // mtile 0
    uint32_t aaddr1 = aaddr0 + 16 * PADBY;                               // mtile 1
    // B x4 (one ntile, two ksteps): matrices at k-offsets 0,4,8,12
    uint32_t baddr = sb + SM_B_OFF + (lane & 7) * PADBY + (lane >> 3) * 16;

    float acc[2][16][4];
#pragma unroll
    for (int mt = 0; mt < 2; mt++)
#pragma unroll
        for (int nt = 0; nt < 16; nt++)
#pragma unroll
            for (int q = 0; q < 4; q++) acc[mt][nt][q] = 0.0f;

#pragma unroll 1
    for (int ks2 = 0; ks2 < 8; ks2++) {
        uint32_t ke = ks2 * 64;           // even kstep byte offset (16 floats)
        uint32_t ko = ke + 32;            // odd kstep
        uint32_t ae[2][4], ao[2][4];
        ldsm4(ae[0], aaddr0 + ke);
        ldsm4(ae[1], aaddr1 + ke);
        ldsm4(ao[0], aaddr0 + ko);
        ldsm4(ao[1], aaddr1 + ko);
#pragma unroll
        for (int nt = 0; nt < 16; nt++) {
            uint32_t b[4];
            ldsm4(b, baddr + nt * (8 * PADBY) + ke);
            mma_tf32(acc[0][nt], ae[0], b[0], b[1]);
            mma_tf32(acc[1][nt], ae[1], b[0], b[1]);
            mma_tf32(acc[0][nt], ao[0], b[2], b[3]);
            mma_tf32(acc[1][nt], ao[1], b[2], b[3]);
        }
    }

    // ---- Epilogue: bias + ReLU, direct vectorized stores ----
#pragma unroll
    for (int nt = 0; nt < 16; nt++) {
        int col = nt * 8 + (lane & 3) * 2;
        float2 bv = *(const float2*)(bias + col);
#pragma unroll
        for (int mt = 0; mt < 2; mt++) {
            int r0 = row0 + wid * 32 + mt * 16 + (lane >> 2);
            float* a = acc[mt][nt];
            float v0 = a[0] + bv.x, v1 = a[1] + bv.y;
            float v2 = a[2] + bv.x, v3 = a[3] + bv.y;
            if (relu) {
                v0 = fmaxf(v0, 0.f); v1 = fmaxf(v1, 0.f);
                v2 = fmaxf(v2, 0.f); v3 = fmaxf(v3, 0.f);
            }
            if (r0 < n)     *(float2*)(C + (size_t)r0 * 128 + col) = make_float2(v0, v1);
            if (r0 + 8 < n) *(float2*)(C + (size_t)(r0 + 8) * 128 + col) = make_float2(v2, v3);
        }
    }
}

// ---------------------------------------------------------------------------
extern "C" void kernel_launch(void* const* d_in, const int* in_sizes, int n_in,
                              void* d_out, int out_size) {
    const float* x   = (const float*)d_in[0];
    const void*  ei  = d_in[1];
    const float* W1  = (const float*)d_in[2];
    const float* b1  = (const float*)d_in[3];
    const float* W2  = (const float*)d_in[4];
    const float* b2  = (const float*)d_in[5];
    const float* eps = (const float*)d_in[6];

    int N = in_sizes[0] / DIM;
    int E = in_sizes[1] / 2;

    float *agg_ptr, *h1_ptr, *wt1_ptr, *wt2_ptr;
    int* cnt_ptr;
    cudaGetSymbolAddress((void**)&agg_ptr, g_agg);
    cudaGetSymbolAddress((void**)&h1_ptr,  g_h1);
    cudaGetSymbolAddress((void**)&wt1_ptr, g_wt1);
    cudaGetSymbolAddress((void**)&wt2_ptr, g_wt2);
    cudaGetSymbolAddress((void**)&cnt_ptr, g_cnt);

    detect_kernel<<<1, 32>>>((const unsigned int*)ei);
    prep_w_kernel<<<(2 * DIM * DIM + 255) / 256, 256>>>(W1, W2);

    if (E <= EDGES_MAX && N <= NNODES) {
        cudaMemsetAsync(cnt_ptr, 0, (size_t)N * sizeof(int), 0);
        int nthr4 = (E + 3) / 4;
        hist_kernel<<<(nthr4 + 255) / 256, 256>>>(ei, E);
        int nb_scan = (N + SCAN_BLK - 1) / SCAN_BLK;
        scan1_kernel<<<nb_scan, 512>>>(N);
        scan2_kernel<<<1, 32>>>(nb_scan);
        scan3_kernel<<<(N + 255) / 256, 256>>>(N, E);
        reorder_kernel<<<(nthr4 + 255) / 256, 256>>>(ei, E);
        agg_kernel<<<(N * 32 + 255) / 256, 256>>>((const float4*)x, eps, N);
    } else {
        int n4 = N * (DIM / 4);
        init_kernel<<<(n4 + 255) / 256, 256>>>((const float4*)x, eps, n4);
        long long tot = (long long)E * 32;
        scatter_kernel<<<(int)((tot + 255) / 256), 256>>>((const float4*)x, ei, E);
    }

    cudaFuncSetAttribute(gemm_tf32_kernel,
                         cudaFuncAttributeMaxDynamicSharedMemorySize,
                         SMEM_GEMM_BYTES);
    int nb = (N + 255) / 256;
    gemm_tf32_kernel<<<nb, 256, SMEM_GEMM_BYTES>>>(agg_ptr, wt1_ptr, b1,
                                                   h1_ptr, N, 1);
    gemm_tf32_kernel<<<nb, 256, SMEM_GEMM_BYTES>>>(h1_ptr, wt2_ptr, b2,
                                                   (float*)d_out, N, 0);
}

// round 8
// speedup vs baseline: 1.1901x; 1.1003x over previous
#include <cuda_runtime.h>
#include <cuda_bf16.h>
#include <cstdint>

#define NNODES 100000
#define EDGES_MAX 1600000
#define DIM 128
#define SCAN_BLK 512
#define NB_SCAN ((NNODES + SCAN_BLK - 1) / SCAN_BLK)

// ---------------------------------------------------------------------------
// Device-global scratch (no allocations allowed anywhere)
// ---------------------------------------------------------------------------
__device__ float g_agg[NNODES * DIM];
__device__ float g_h1[NNODES * DIM];      // used only by fallback path
__device__ int   g_is64;
__device__ float g_wt1[DIM * DIM];   // W1^T, tf32-rounded fp32, [n][k]
__device__ float g_wt2[DIM * DIM];   // W2^T, tf32-rounded fp32, [n][k]
// CSR build
__device__ int g_cnt[NNODES];
__device__ int g_rowptr[NNODES + 1];
__device__ int g_cur[NNODES];
__device__ int g_blksum[NB_SCAN + 8];
__device__ int g_esrc[EDGES_MAX];

// ---------------------------------------------------------------------------
// helpers
// ---------------------------------------------------------------------------
__device__ __forceinline__ uint32_t smem_u32(const void* p) {
    uint32_t a;
    asm("{ .reg .u64 t; cvta.to.shared.u64 t, %1; cvt.u32.u64 %0, t; }"
        : "=r"(a) : "l"(p));
    return a;
}
__device__ __forceinline__ void ldsm4(uint32_t* r, uint32_t addr) {
    asm volatile("ldmatrix.sync.aligned.m8n8.x4.shared.b16 {%0,%1,%2,%3}, [%4];"
                 : "=r"(r[0]), "=r"(r[1]), "=r"(r[2]), "=r"(r[3]) : "r"(addr));
}
__device__ __forceinline__ void mma_tf32(float* d, const uint32_t* a,
                                         uint32_t b0, uint32_t b1) {
    asm volatile(
        "mma.sync.aligned.m16n8k8.row.col.f32.tf32.tf32.f32 "
        "{%0,%1,%2,%3}, {%4,%5,%6,%7}, {%8,%9}, {%0,%1,%2,%3};"
        : "+f"(d[0]), "+f"(d[1]), "+f"(d[2]), "+f"(d[3])
        : "r"(a[0]), "r"(a[1]), "r"(a[2]), "r"(a[3]), "r"(b0), "r"(b1));
}
__device__ __forceinline__ uint32_t f2tf32(float f) {
    uint32_t r;
    asm("cvt.rna.tf32.f32 %0, %1;" : "=r"(r) : "f"(f));
    return r;
}
__device__ __forceinline__ int load_idx(const void* ei, long long pos) {
    return g_is64 ? (int)((const long long*)ei)[pos] : ((const int*)ei)[pos];
}

// ---------------------------------------------------------------------------
// edge_index dtype detection (int64 ids < 2^31 -> odd words all zero)
// ---------------------------------------------------------------------------
__global__ void detect_kernel(const unsigned int* __restrict__ w) {
    if (threadIdx.x == 0 && blockIdx.x == 0) {
        int allzero = 1;
        for (int i = 1; i < 256; i += 2)
            if (w[i] != 0u) { allzero = 0; break; }
        g_is64 = allzero;
    }
}

// ---------------------------------------------------------------------------
// CSR build: histogram -> scan (512/block, shfl) -> reorder
// (g_cnt is zeroed by cudaMemsetAsync in kernel_launch)
// ---------------------------------------------------------------------------
__global__ void hist_kernel(const void* __restrict__ ei, int E) {
    int i0 = (blockIdx.x * blockDim.x + threadIdx.x) * 4;
    if (i0 + 4 <= E) {
        int d0 = load_idx(ei, (long long)E + i0);
        int d1 = load_idx(ei, (long long)E + i0 + 1);
        int d2 = load_idx(ei, (long long)E + i0 + 2);
        int d3 = load_idx(ei, (long long)E + i0 + 3);
        atomicAdd(&g_cnt[d0], 1);
        atomicAdd(&g_cnt[d1], 1);
        atomicAdd(&g_cnt[d2], 1);
        atomicAdd(&g_cnt[d3], 1);
    } else {
        for (int i = i0; i < E; i++)
            atomicAdd(&g_cnt[load_idx(ei, (long long)E + i)], 1);
    }
}

__device__ __forceinline__ int warp_incl_scan(int x, int lane) {
#pragma unroll
    for (int off = 1; off < 32; off <<= 1) {
        int y = __shfl_up_sync(0xFFFFFFFFu, x, off);
        if (lane >= off) x += y;
    }
    return x;
}

__global__ void scan1_kernel(int N) {  // 512 threads, 1 elem each
    __shared__ int wsum[16];
    int t = threadIdx.x, b = blockIdx.x;
    int lane = t & 31, wd = t >> 5;
    int idx = b * SCAN_BLK + t;
    int v = (idx < N) ? g_cnt[idx] : 0;
    int incl = warp_incl_scan(v, lane);
    if (lane == 31) wsum[wd] = incl;
    __syncthreads();
    if (wd == 0) {
        int s = (lane < 16) ? wsum[lane] : 0;
        s = warp_incl_scan(s, lane);
        if (lane < 16) wsum[lane] = s;
    }
    __syncthreads();
    int base = (wd > 0) ? wsum[wd - 1] : 0;
    incl += base;
    if (idx < N) g_rowptr[idx] = incl - v;   // exclusive
    if (t == SCAN_BLK - 1) g_blksum[b] = incl;
}

__global__ void scan2_kernel(int nb) {  // one 256-thread block; nb <= 256
    __shared__ int wsum[8];
    int t = threadIdx.x, lane = t & 31, wd = t >> 5;
    int v = (t < nb) ? g_blksum[t] : 0;
    int incl = warp_incl_scan(v, lane);
    if (lane == 31) wsum[wd] = incl;
    __syncthreads();
    if (wd == 0) {
        int s = (lane < 8) ? wsum[lane] : 0;
        s = warp_incl_scan(s, lane);
        if (lane < 8) wsum[lane] = s;
    }
    __syncthreads();
    int base = (wd > 0) ? wsum[wd - 1] : 0;
    if (t < nb) g_blksum[t] = incl + base - v;  // exclusive
}

__global__ void scan3_kernel(int N, int E) {
    int i = blockIdx.x * blockDim.x + threadIdx.x;
    if (i < N) {
        int v = g_rowptr[i] + g_blksum[i / SCAN_BLK];
        g_rowptr[i] = v;
        g_cur[i] = v;
    }
    if (i == 0) g_rowptr[N] = E;
}

__global__ void reorder_kernel(const void* __restrict__ ei, int E) {
    int i0 = (blockIdx.x * blockDim.x + threadIdx.x) * 4;
    if (i0 + 4 <= E) {
        int s0 = load_idx(ei, i0),     s1 = load_idx(ei, i0 + 1);
        int s2 = load_idx(ei, i0 + 2), s3 = load_idx(ei, i0 + 3);
        int d0 = load_idx(ei, (long long)E + i0);
        int d1 = load_idx(ei, (long long)E + i0 + 1);
        int d2 = load_idx(ei, (long long)E + i0 + 2);
        int d3 = load_idx(ei, (long long)E + i0 + 3);
        g_esrc[atomicAdd(&g_cur[d0], 1)] = s0;
        g_esrc[atomicAdd(&g_cur[d1], 1)] = s1;
        g_esrc[atomicAdd(&g_cur[d2], 1)] = s2;
        g_esrc[atomicAdd(&g_cur[d3], 1)] = s3;
    } else {
        for (int i = i0; i < E; i++) {
            int src = load_idx(ei, i);
            int dst = load_idx(ei, (long long)E + i);
            g_esrc[atomicAdd(&g_cur[dst], 1)] = src;
        }
    }
}

// ---------------------------------------------------------------------------
// Aggregation: one warp per node. agg[i] = (1+eps)*x[i] + sum_j x[esrc[j]].
// fp32 float4 gathers, unroll-8 for MLP depth.
// ---------------------------------------------------------------------------
__global__ void agg_kernel(const float4* __restrict__ x,
                           const float* __restrict__ eps, int N) {
    int w = (blockIdx.x * blockDim.x + threadIdx.x) >> 5;
    if (w >= N) return;
    int lane = threadIdx.x & 31;
    float s = 1.0f + eps[0];

    float4 a = x[(size_t)w * 32 + lane];
    float4 acc = make_float4(a.x * s, a.y * s, a.z * s, a.w * s);

    int j  = g_rowptr[w];
    int r1 = g_rowptr[w + 1];

#pragma unroll 1
    for (; j + 8 <= r1; j += 8) {
        int idx[8];
#pragma unroll
        for (int q = 0; q < 8; q++) idx[q] = g_esrc[j + q];
        float4 v[8];
#pragma unroll
        for (int q = 0; q < 8; q++) v[q] = x[(size_t)idx[q] * 32 + lane];
#pragma unroll
        for (int q = 0; q < 8; q++) {
            acc.x += v[q].x; acc.y += v[q].y;
            acc.z += v[q].z; acc.w += v[q].w;
        }
    }
    for (; j + 4 <= r1; j += 4) {
        int s0 = g_esrc[j],     s1 = g_esrc[j + 1];
        int s2 = g_esrc[j + 2], s3 = g_esrc[j + 3];
        float4 v0 = x[(size_t)s0 * 32 + lane];
        float4 v1 = x[(size_t)s1 * 32 + lane];
        float4 v2 = x[(size_t)s2 * 32 + lane];
        float4 v3 = x[(size_t)s3 * 32 + lane];
        acc.x += v0.x + v1.x + v2.x + v3.x;
        acc.y += v0.y + v1.y + v2.y + v3.y;
        acc.z += v0.z + v1.z + v2.z + v3.z;
        acc.w += v0.w + v1.w + v2.w + v3.w;
    }
    for (; j < r1; j++) {
        float4 v = x[(size_t)g_esrc[j] * 32 + lane];
        acc.x += v.x; acc.y += v.y; acc.z += v.z; acc.w += v.w;
    }
    ((float4*)g_agg)[(size_t)w * 32 + lane] = acc;
}

// ---------------------------------------------------------------------------
// Legacy fallback path (if E > EDGES_MAX): init + atomic scatter
// ---------------------------------------------------------------------------
__global__ void init_kernel(const float4* __restrict__ x,
                            const float* __restrict__ eps, int n4) {
    float s = 1.0f + eps[0];
    float4* agg = (float4*)g_agg;
    int i = blockIdx.x * blockDim.x + threadIdx.x;
    int stride = gridDim.x * blockDim.x;
    for (; i < n4; i += stride) {
        float4 v = x[i];
        v.x *= s; v.y *= s; v.z *= s; v.w *= s;
        agg[i] = v;
    }
}

__global__ void scatter_kernel(const float4* __restrict__ x,
                               const void* __restrict__ ei, int E) {
    int t = blockIdx.x * blockDim.x + threadIdx.x;
    int e = t >> 5;
    if (e >= E) return;
    int lane = t & 31;
    int src = load_idx(ei, e);
    int dst = load_idx(ei, (long long)E + e);
    float4 v = x[(size_t)src * 32 + lane];
    float* q = g_agg + (size_t)dst * 128 + lane * 4;
    asm volatile("red.global.add.v4.f32 [%0], {%1,%2,%3,%4};"
                 :: "l"(q), "f"(v.x), "f"(v.y), "f"(v.z), "f"(v.w)
                 : "memory");
}

// ---------------------------------------------------------------------------
// Weight prep: Wt[n][k] = tf32_round(W[k][n])  (fp32 bit pattern)
// ---------------------------------------------------------------------------
__global__ void prep_w_kernel(const float* __restrict__ W1,
                              const float* __restrict__ W2) {
    int i = blockIdx.x * blockDim.x + threadIdx.x;
    if (i >= 2 * DIM * DIM) return;
    const float* W = (i < DIM * DIM) ? W1 : W2;
    float* T = (i < DIM * DIM) ? g_wt1 : g_wt2;
    int j = i & (DIM * DIM - 1);
    int nIdx = j >> 7;
    int k = j & 127;
    uint32_t t = f2tf32(W[k * DIM + nIdx]);
    T[j] = __uint_as_float(t);
}

// ---------------------------------------------------------------------------
// Fused 2-layer TF32 tensor-core GEMM:
//   out[n,128] = relu(A @ W1 + b1) @ W2 + b2
// One CTA per 256-row tile, 8 warps x 32 rows (2 m-tiles of 16/warp).
// Layer-1 epilogue writes relu'd tf32 h1 back into the smem A buffer
// (W2 restaged into B buffer behind the same sync) -> no h1 gmem round-trip.
// Smem rows padded to 132 floats (528B) for conflict-free b32 ldmatrix.
// ---------------------------------------------------------------------------
#define PADBY 528                      // bytes per padded row
#define SM_B_OFF 135168                // 256*528
#define SMEM_GEMM_BYTES 202752         // 256*528 + 128*528

struct Frag { float v[2][16][4]; };

__device__ __forceinline__ void tf32_mainloop(uint32_t aaddr0, uint32_t aaddr1,
                                              uint32_t baddr, Frag& f) {
#pragma unroll
    for (int mt = 0; mt < 2; mt++)
#pragma unroll
        for (int nt = 0; nt < 16; nt++)
#pragma unroll
            for (int q = 0; q < 4; q++) f.v[mt][nt][q] = 0.0f;

#pragma unroll 1
    for (int ks2 = 0; ks2 < 8; ks2++) {
        uint32_t ke = ks2 * 64;           // even kstep byte offset
        uint32_t ko = ke + 32;            // odd kstep
        uint32_t ae[2][4], ao[2][4];
        ldsm4(ae[0], aaddr0 + ke);
        ldsm4(ae[1], aaddr1 + ke);
        ldsm4(ao[0], aaddr0 + ko);
        ldsm4(ao[1], aaddr1 + ko);
#pragma unroll
        for (int nt = 0; nt < 16; nt++) {
            uint32_t b[4];
            ldsm4(b, baddr + nt * (8 * PADBY) + ke);
            mma_tf32(f.v[0][nt], ae[0], b[0], b[1]);
            mma_tf32(f.v[1][nt], ae[1], b[0], b[1]);
            mma_tf32(f.v[0][nt], ao[0], b[2], b[3]);
            mma_tf32(f.v[1][nt], ao[1], b[2], b[3]);
        }
    }
}

__global__ void __launch_bounds__(256, 1)
gemm_fused_kernel(const float* __restrict__ A,
                  const float* __restrict__ B1t,
                  const float* __restrict__ b1,
                  const float* __restrict__ B2t,
                  const float* __restrict__ b2,
                  float* __restrict__ out, int n) {
    extern __shared__ char smem[];
    uint32_t sb = smem_u32(smem);
    int tid = threadIdx.x, wid = tid >> 5, lane = tid & 31;
    int row0 = blockIdx.x * 256;

    // ---- Stage A (tf32-rounded) ----
    const float4* A4 = (const float4*)A;
#pragma unroll
    for (int i = 0; i < 32; i++) {
        int idx = tid + 256 * i;
        int r = idx >> 5, c4 = idx & 31;
        int gr = row0 + r;
        float4 v = (gr < n) ? A4[(size_t)gr * 32 + c4]
                            : make_float4(0.f, 0.f, 0.f, 0.f);
        uint4 o;
        o.x = f2tf32(v.x); o.y = f2tf32(v.y);
        o.z = f2tf32(v.z); o.w = f2tf32(v.w);
        *(uint4*)(smem + r * PADBY + c4 * 16) = o;
    }

    // ---- Stage B = W1t ----
    const float4* B4 = (const float4*)B1t;
#pragma unroll
    for (int i = 0; i < 16; i++) {
        int idx = tid + 256 * i;
        int r = idx >> 5, c4 = idx & 31;
        *(float4*)(smem + SM_B_OFF + r * PADBY + c4 * 16) = B4[idx];
    }
    __syncthreads();

    // ---- Per-lane ldmatrix addresses ----
    int mi = lane >> 3;
    int arow_base = wid * 32 + (mi & 1) * 8 + (lane & 7);
    uint32_t aaddr0 = sb + arow_base * PADBY + (mi >> 1) * 16;
    uint32_t aaddr1 = aaddr0 + 16 * PADBY;
    uint32_t baddr = sb + SM_B_OFF + (lane & 7) * PADBY + (lane >> 3) * 16;

    Frag f;
    // ================= Layer 1 =================
    tf32_mainloop(aaddr0, aaddr1, baddr, f);
    __syncthreads();   // everyone done reading smem A & B

    // ---- Restage B = W2t ----
    const float4* B24 = (const float4*)B2t;
#pragma unroll
    for (int i = 0; i < 16; i++) {
        int idx = tid + 256 * i;
        int r = idx >> 5, c4 = idx & 31;
        *(float4*)(smem + SM_B_OFF + r * PADBY + c4 * 16) = B24[idx];
    }

    // ---- Layer-1 epilogue into smem A: h1 = tf32(relu(acc + b1)) ----
#pragma unroll
    for (int nt = 0; nt < 16; nt++) {
        int col = nt * 8 + (lane & 3) * 2;
        float2 bv = *(const float2*)(b1 + col);
#pragma unroll
        for (int mt = 0; mt < 2; mt++) {
            int lr = wid * 32 + mt * 16 + (lane >> 2);
            float* a = f.v[mt][nt];
            uint2 p0, p1;
            p0.x = f2tf32(fmaxf(a[0] + bv.x, 0.f));
            p0.y = f2tf32(fmaxf(a[1] + bv.y, 0.f));
            p1.x = f2tf32(fmaxf(a[2] + bv.x, 0.f));
            p1.y = f2tf32(fmaxf(a[3] + bv.y, 0.f));
            *(uint2*)(smem + lr * PADBY + col * 4)       = p0;
            *(uint2*)(smem + (lr + 8) * PADBY + col * 4) = p1;
        }
    }
    __syncthreads();

    // ================= Layer 2 =================
    tf32_mainloop(aaddr0, aaddr1, baddr, f);

    // ---- Final epilogue to gmem: out = acc + b2 ----
#pragma unroll
    for (int nt = 0; nt < 16; nt++) {
        int col = nt * 8 + (lane & 3) * 2;
        float2 bv = *(const float2*)(b2 + col);
#pragma unroll
        for (int mt = 0; mt < 2; mt++) {
            int r0 = row0 + wid * 32 + mt * 16 + (lane >> 2);
            float* a = f.v[mt][nt];
            if (r0 < n)
                *(float2*)(out + (size_t)r0 * 128 + col) =
                    make_float2(a[0] + bv.x, a[1] + bv.y);
            if (r0 + 8 < n)
                *(float2*)(out + (size_t)(r0 + 8) * 128 + col) =
                    make_float2(a[2] + bv.x, a[3] + bv.y);
        }
    }
}

// ---------------------------------------------------------------------------
extern "C" void kernel_launch(void* const* d_in, const int* in_sizes, int n_in,
                              void* d_out, int out_size) {
    const float* x   = (const float*)d_in[0];
    const void*  ei  = d_in[1];
    const float* W1  = (const float*)d_in[2];
    const float* b1  = (const float*)d_in[3];
    const float* W2  = (const float*)d_in[4];
    const float* b2  = (const float*)d_in[5];
    const float* eps = (const float*)d_in[6];

    int N = in_sizes[0] / DIM;
    int E = in_sizes[1] / 2;

    float *agg_ptr, *wt1_ptr, *wt2_ptr;
    int* cnt_ptr;
    cudaGetSymbolAddress((void**)&agg_ptr, g_agg);
    cudaGetSymbolAddress((void**)&wt1_ptr, g_wt1);
    cudaGetSymbolAddress((void**)&wt2_ptr, g_wt2);
    cudaGetSymbolAddress((void**)&cnt_ptr, g_cnt);

    detect_kernel<<<1, 32>>>((const unsigned int*)ei);
    prep_w_kernel<<<(2 * DIM * DIM + 255) / 256, 256>>>(W1, W2);

    if (E <= EDGES_MAX && N <= NNODES) {
        cudaMemsetAsync(cnt_ptr, 0, (size_t)N * sizeof(int), 0);
        int nthr4 = (E + 3) / 4;
        hist_kernel<<<(nthr4 + 255) / 256, 256>>>(ei, E);
        int nb_scan = (N + SCAN_BLK - 1) / SCAN_BLK;
        scan1_kernel<<<nb_scan, SCAN_BLK>>>(N);
        scan2_kernel<<<1, 256>>>(nb_scan);
        scan3_kernel<<<(N + 255) / 256, 256>>>(N, E);
        reorder_kernel<<<(nthr4 + 255) / 256, 256>>>(ei, E);
        agg_kernel<<<(N * 32 + 255) / 256, 256>>>((const float4*)x, eps, N);
    } else {
        int n4 = N * (DIM / 4);
        init_kernel<<<(n4 + 255) / 256, 256>>>((const float4*)x, eps, n4);
        long long tot = (long long)E * 32;
        scatter_kernel<<<(int)((tot + 255) / 256), 256>>>((const float4*)x, ei, E);
    }

    cudaFuncSetAttribute(gemm_fused_kernel,
                         cudaFuncAttributeMaxDynamicSharedMemorySize,
                         SMEM_GEMM_BYTES);
    int nb = (N + 255) / 256;
    gemm_fused_kernel<<<nb, 256, SMEM_GEMM_BYTES>>>(agg_ptr, wt1_ptr, b1,
                                                    wt2_ptr, b2,
                                                    (float*)d_out, N);
}